// round 11
// baseline (speedup 1.0000x reference)
#include <cuda_runtime.h>

// Blocks_86096914416144 — SNN block scan, R11: R5 body (57.8us champion) with
// the membrane sums and threshold math packed into f32x2 instructions
// (fma/mul/add/sub.rn.f32x2 = two independent rn ops, identical rounding per
// lane). Pads are trailing +/-0 terms only (R9-proven exact); m[7] unpadded so
// vmem is bit-exact. Head recompute / a-chain / cumsum+store = EXACT R5.
// Evidence R5-R10: wall = 128 x per-warp iter time; cuts must not deepen chains.

#define T_LEN   1024
#define TB      8
#define NBLK    (T_LEN / TB)      // 128
#define BATCH   32
#define NOUT    1024
#define BN      (BATCH * NOUT)    // 32768
#define CTA     128

typedef unsigned long long u64;

__device__ __forceinline__ u64 pk2(float lo, float hi) {
    u64 r; asm("mov.b64 %0, {%1, %2};" : "=l"(r) : "f"(lo), "f"(hi)); return r;
}
__device__ __forceinline__ void upk2(u64 v, float& lo, float& hi) {
    asm("mov.b64 {%0, %1}, %2;" : "=f"(lo), "=f"(hi) : "l"(v));
}
__device__ __forceinline__ u64 fma2(u64 a, u64 b, u64 c) {
    u64 d; asm("fma.rn.f32x2 %0, %1, %2, %3;" : "=l"(d) : "l"(a), "l"(b), "l"(c)); return d;
}
__device__ __forceinline__ u64 mul2(u64 a, u64 b) {
    u64 d; asm("mul.rn.f32x2 %0, %1, %2;" : "=l"(d) : "l"(a), "l"(b)); return d;
}
__device__ __forceinline__ u64 add2(u64 a, u64 b) {
    u64 d; asm("add.rn.f32x2 %0, %1, %2;" : "=l"(d) : "l"(a), "l"(b)); return d;
}
__device__ __forceinline__ u64 sub2(u64 a, u64 b) {
    u64 d; asm("sub.rn.f32x2 %0, %1, %2;" : "=l"(d) : "l"(a), "l"(b)); return d;
}

__global__ __launch_bounds__(CTA)
void blocks_snn_kernel(const float* __restrict__ x,
                       const float* __restrict__ beta_raw,
                       const float* __restrict__ p_raw,
                       const float* __restrict__ b_raw,
                       float* __restrict__ out)
{
    const int tid = blockIdx.x * CTA + threadIdx.x;   // 0..32767
    const int n   = tid & (NOUT - 1);

    const float beta  = fminf(fmaxf(beta_raw[n], 0.001f), 0.999f);
    const float p     = fminf(fmaxf(fabsf(p_raw[n]), 0.0f), 0.999f);
    const float bb    = fminf(fmaxf(fabsf(b_raw[n]), 0.001f), 1.0f);
    const float inv_p = 1.0f / p;

    float bpow[TB];
    bpow[0] = 1.0f;
    #pragma unroll
    for (int k = 1; k < TB; k++) bpow[k] = powf(beta, (float)k);

    float ppow[TB + 1];
    ppow[0] = 1.0f;
    #pragma unroll
    for (int k = 1; k <= TB; k++) ppow[k] = powf(p, (float)k);

    // packed weight pairs: wp[i] = {bpow[i-1] (0 if i==0), bpow[i]}
    // pair j (t=2j lo, t=2j+1 hi) at step s uses wp[2j+1-s].
    u64 wp[TB];
    wp[0] = pk2(0.0f, bpow[0]);
    #pragma unroll
    for (int i = 1; i < TB; i++) wp[i] = pk2(bpow[i - 1], bpow[i]);

    // packed vth constants: pp2[j] = {ppow[2j+1], ppow[2j+2]}
    u64 pp2[4];
    #pragma unroll
    for (int j = 0; j < 4; j++) pp2[j] = pk2(ppow[2 * j + 1], ppow[2 * j + 2]);
    const u64 bb2  = pk2(bb, bb);
    const u64 one2 = pk2(1.0f, 1.0f);

    // carry state (exact R5)
    float z[TB];
    #pragma unroll
    for (int t = 0; t < TB; t++) z[t] = 0.0f;
    float a    = 0.0f;
    float vmem = 0.0f;

    const float* xp = x + tid;
    float*       op = out + tid;

    // 4-slot register ring, prefetch 3 blocks ahead (exact R5)
    float buf[4][TB];
    #pragma unroll
    for (int pb = 0; pb < 3; pb++) {
        const float* xb = xp + (size_t)pb * TB * BN;
        #pragma unroll
        for (int t = 0; t < TB; t++) buf[pb][t] = xb[t * BN];
    }

    #pragma unroll 1
    for (int g = 0; g < NBLK / 4; g++) {
        #pragma unroll
        for (int u = 0; u < 4; u++) {
            const int blk = 4 * g + u;

            if (blk + 3 < NBLK) {
                const float* xb = xp + (size_t)(blk + 3) * TB * BN;
                #pragma unroll
                for (int t = 0; t < TB; t++)
                    buf[(u + 3) & 3][t] = xb[t * BN];
            }
            const float* xc = buf[u & 3];

            // ---- head: sg, maskf, ds from z (exact R5) ----
            float sg[TB];
            float maskf = 0.0f;
            #pragma unroll
            for (int t = 0; t < TB; t++) {
                sg[t] = (z[t] == 1.0f) ? 1.0f : 0.0f;
                if (sg[t] != 0.0f) maskf = 1.0f;
            }

            float a_at = 0.0f;
            #pragma unroll
            for (int t = 0; t < TB; t++)
                if (sg[t] != 0.0f) a_at += ppow[t + 1] * a;
            a_at += inv_p;

            int ds = 0;
            #pragma unroll
            for (int t = 0; t < TB; t++)
                if (z[t] > 1.0f) ds++;

            float pds = ppow[0];
            #pragma unroll
            for (int k = 1; k <= TB; k++)
                if (ds == k) pds = ppow[k];

            const float new_a = a_at * pds;
            a = (maskf != 0.0f) ? new_a : (ppow[TB] * a);

            // ---- refractory masking + carry-in (exact R5) ----
            const float v_init = vmem * (1.0f - maskf);
            float cur[TB];
            #pragma unroll
            for (int t = 0; t < TB; t++)
                cur[t] = (z[t] < maskf) ? 0.0f : xc[t];
            cur[0] = cur[0] + beta * v_init;

            // ---- packed causal sums: pair j = (t=2j lo, t=2j+1 hi) ----
            // lo lane: real terms s=0..2j ascending, then one trailing +/-0 pad.
            // hi lane: real terms s=0..2j+1 ascending, no pad. (exact)
            u64 curp[TB];
            #pragma unroll
            for (int s = 0; s < TB; s++) curp[s] = pk2(cur[s], cur[s]);

            u64 accs[4];
            #pragma unroll
            for (int j = 0; j < 4; j++) {
                u64 acc = pk2(0.0f, 0.0f);
                #pragma unroll
                for (int s = 0; s <= 2 * j + 1; s++)
                    acc = fma2(wp[2 * j + 1 - s], curp[s], acc);
                accs[j] = acc;
            }

            // ---- packed vth + diff; scalar threshold bits ----
            const u64 a2 = pk2(a, a);
            float f[TB];
            float mlast = 0.0f;
            #pragma unroll
            for (int j = 0; j < 4; j++) {
                // vth = 1 + bb*(ppow[t+1]*a)  (reference order per lane)
                const u64 vth2 = add2(one2, mul2(bb2, mul2(pp2[j], a2)));
                const u64 d2   = sub2(accs[j], vth2);
                float dlo, dhi;
                upk2(d2, dlo, dhi);
                f[2 * j]     = (dlo > 0.0f) ? 1.0f : 0.0f;
                f[2 * j + 1] = (dhi > 0.0f) ? 1.0f : 0.0f;
                if (j == 3) {
                    float mlo;
                    upk2(accs[3], mlo, mlast);   // hi lane = m[7], bit-exact
                }
            }

            // ---- z = double cumsum; emit spikes (exact R5) ----
            float* ob = op + (size_t)blk * TB * BN;
            float c = 0.0f, zr = 0.0f;
            #pragma unroll
            for (int t = 0; t < TB; t++) {
                c  += f[t];
                zr += c;
                z[t] = zr;
                ob[t * BN] = (zr == 1.0f) ? 1.0f : 0.0f;
            }

            vmem = mlast;
        }
    }
}

extern "C" void kernel_launch(void* const* d_in, const int* in_sizes, int n_in,
                              void* d_out, int out_size)
{
    const float* x        = (const float*)d_in[0];
    const float* beta_raw = (const float*)d_in[1];
    const float* p_raw    = (const float*)d_in[2];
    const float* b_raw    = (const float*)d_in[3];
    float* out = (float*)d_out;

    blocks_snn_kernel<<<BN / CTA, CTA>>>(x, beta_raw, p_raw, b_raw, out);
}

// round 12
// speedup vs baseline: 1.1213x; 1.1213x over previous
#include <cuda_runtime.h>

// Blocks_86096914416144 — SNN block scan, R12: R5 body BIT-IDENTICAL (57.8us
// champion), plus software-pipelined stores: iteration i's 8 STG are deferred
// and issued at the top of iteration i+1, overlapping the store burst (~40 LSU
// issue cycles) with the next head's compare/FFMA chain. Stores read only a
// pending-register copy; zero FP changes -> rel_err 0.0 guaranteed.
// Law learned R5-R11: wall = 128 x per-warp iter time; only overlap, never
// restructure (every restructure raised cyc/instr).

#define T_LEN   1024
#define TB      8
#define NBLK    (T_LEN / TB)      // 128
#define BATCH   32
#define NOUT    1024
#define BN      (BATCH * NOUT)    // 32768
#define CTA     128

__global__ __launch_bounds__(CTA)
void blocks_snn_kernel(const float* __restrict__ x,
                       const float* __restrict__ beta_raw,
                       const float* __restrict__ p_raw,
                       const float* __restrict__ b_raw,
                       float* __restrict__ out)
{
    const int tid = blockIdx.x * CTA + threadIdx.x;   // 0..32767
    const int n   = tid & (NOUT - 1);

    const float beta  = fminf(fmaxf(beta_raw[n], 0.001f), 0.999f);
    const float p     = fminf(fmaxf(fabsf(p_raw[n]), 0.0f), 0.999f);
    const float bb    = fminf(fmaxf(fabsf(b_raw[n]), 0.001f), 1.0f);
    const float inv_p = 1.0f / p;

    float bpow[TB];
    bpow[0] = 1.0f;
    #pragma unroll
    for (int k = 1; k < TB; k++) bpow[k] = powf(beta, (float)k);

    float ppow[TB + 1];
    ppow[0] = 1.0f;
    #pragma unroll
    for (int k = 1; k <= TB; k++) ppow[k] = powf(p, (float)k);

    // carry state (exact R5)
    float z[TB];
    #pragma unroll
    for (int t = 0; t < TB; t++) z[t] = 0.0f;
    float a    = 0.0f;
    float vmem = 0.0f;

    const float* xp = x + tid;
    float*       op = out + tid;

    // 4-slot register ring, prefetch 3 blocks ahead (exact R5)
    float buf[4][TB];
    #pragma unroll
    for (int pb = 0; pb < 3; pb++) {
        const float* xb = xp + (size_t)pb * TB * BN;
        #pragma unroll
        for (int t = 0; t < TB; t++) buf[pb][t] = xb[t * BN];
    }

    // pending (deferred) stores
    float  pend[TB];
    float* pendp = op;            // valid only when havep
    bool   havep = false;

    #pragma unroll 1
    for (int g = 0; g < NBLK / 4; g++) {
        #pragma unroll
        for (int u = 0; u < 4; u++) {
            const int blk = 4 * g + u;

            // ---- prefetch blk+3 (exact R5) ----
            if (blk + 3 < NBLK) {
                const float* xb = xp + (size_t)(blk + 3) * TB * BN;
                #pragma unroll
                for (int t = 0; t < TB; t++)
                    buf[(u + 3) & 3][t] = xb[t * BN];
            }
            const float* xc = buf[u & 3];

            // ---- flush previous iteration's stores (overlaps with head) ----
            if (havep) {
                #pragma unroll
                for (int t = 0; t < TB; t++)
                    pendp[t * BN] = pend[t];
            }

            // ---- head: sg, maskf from z (exact R5) ----
            float sg[TB];
            float maskf = 0.0f;
            #pragma unroll
            for (int t = 0; t < TB; t++) {
                sg[t] = (z[t] == 1.0f) ? 1.0f : 0.0f;
                if (sg[t] != 0.0f) maskf = 1.0f;
            }

            float a_at = 0.0f;
            #pragma unroll
            for (int t = 0; t < TB; t++)
                if (sg[t] != 0.0f) a_at += ppow[t + 1] * a;
            a_at += inv_p;

            int ds = 0;
            #pragma unroll
            for (int t = 0; t < TB; t++)
                if (z[t] > 1.0f) ds++;

            float pds = ppow[0];
            #pragma unroll
            for (int k = 1; k <= TB; k++)
                if (ds == k) pds = ppow[k];

            const float new_a = a_at * pds;
            a = (maskf != 0.0f) ? new_a : (ppow[TB] * a);

            // ---- refractory masking + carry-in (exact R5) ----
            const float v_init = vmem * (1.0f - maskf);
            float cur[TB];
            #pragma unroll
            for (int t = 0; t < TB; t++)
                cur[t] = (z[t] < maskf) ? 0.0f : xc[t];
            cur[0] = cur[0] + beta * v_init;

            // ---- causal decayed sum + threshold (exact R5) ----
            float f[TB];
            float mlast = 0.0f;
            #pragma unroll
            for (int t = 0; t < TB; t++) {
                float m = 0.0f;
                #pragma unroll
                for (int s = 0; s <= t; s++)
                    m += bpow[t - s] * cur[s];
                const float vth = 1.0f + bb * (ppow[t + 1] * a);
                f[t] = ((m - vth) > 0.0f) ? 1.0f : 0.0f;
                if (t == TB - 1) mlast = m;
            }

            // ---- z = double cumsum; spikes into pending regs (exact values) ----
            float c = 0.0f, zr = 0.0f;
            #pragma unroll
            for (int t = 0; t < TB; t++) {
                c  += f[t];
                zr += c;
                z[t] = zr;
                pend[t] = (zr == 1.0f) ? 1.0f : 0.0f;
            }
            pendp = op + (size_t)blk * TB * BN;
            havep = true;

            vmem = mlast;
        }
    }

    // final flush (block 127)
    #pragma unroll
    for (int t = 0; t < TB; t++)
        pendp[t * BN] = pend[t];
}

extern "C" void kernel_launch(void* const* d_in, const int* in_sizes, int n_in,
                              void* d_out, int out_size)
{
    const float* x        = (const float*)d_in[0];
    const float* beta_raw = (const float*)d_in[1];
    const float* p_raw    = (const float*)d_in[2];
    const float* b_raw    = (const float*)d_in[3];
    float* out = (float*)d_out;

    blocks_snn_kernel<<<BN / CTA, CTA>>>(x, beta_raw, p_raw, b_raw, out);
}

// round 13
// speedup vs baseline: 1.1808x; 1.0531x over previous
#include <cuda_runtime.h>

// Blocks_86096914416144 — SNN block scan, R13: R5 (57.8us champion) with ONE
// pure-scheduling change: membrane sums computed s-major, interleaving the 8
// independent per-t FMA chains (rt=2) instead of running each chain serially
// (lat=4 stalls). Per fixed t, terms still accumulate in ascending s ->
// BIT-IDENTICAL arithmetic to R5. Everything else byte-for-byte R5.
// Law (R5-R12): wall = 128 x per-warp serial time = sum of dependency stalls;
// R8 proved intra-warp ILP cuts it (617 vs 817 cyc per lane-iter).

#define T_LEN   1024
#define TB      8
#define NBLK    (T_LEN / TB)      // 128
#define BATCH   32
#define NOUT    1024
#define BN      (BATCH * NOUT)    // 32768
#define CTA     128

__global__ __launch_bounds__(CTA)
void blocks_snn_kernel(const float* __restrict__ x,
                       const float* __restrict__ beta_raw,
                       const float* __restrict__ p_raw,
                       const float* __restrict__ b_raw,
                       float* __restrict__ out)
{
    const int tid = blockIdx.x * CTA + threadIdx.x;   // 0..32767
    const int n   = tid & (NOUT - 1);

    const float beta  = fminf(fmaxf(beta_raw[n], 0.001f), 0.999f);
    const float p     = fminf(fmaxf(fabsf(p_raw[n]), 0.0f), 0.999f);
    const float bb    = fminf(fmaxf(fabsf(b_raw[n]), 0.001f), 1.0f);
    const float inv_p = 1.0f / p;

    float bpow[TB];
    bpow[0] = 1.0f;
    #pragma unroll
    for (int k = 1; k < TB; k++) bpow[k] = powf(beta, (float)k);

    float ppow[TB + 1];
    ppow[0] = 1.0f;
    #pragma unroll
    for (int k = 1; k <= TB; k++) ppow[k] = powf(p, (float)k);

    // carry state (exact R5)
    float z[TB];
    #pragma unroll
    for (int t = 0; t < TB; t++) z[t] = 0.0f;
    float a    = 0.0f;
    float vmem = 0.0f;

    const float* xp = x + tid;
    float*       op = out + tid;

    // 4-slot register ring, prefetch 3 blocks ahead (exact R5)
    float buf[4][TB];
    #pragma unroll
    for (int pb = 0; pb < 3; pb++) {
        const float* xb = xp + (size_t)pb * TB * BN;
        #pragma unroll
        for (int t = 0; t < TB; t++) buf[pb][t] = xb[t * BN];
    }

    #pragma unroll 1
    for (int g = 0; g < NBLK / 4; g++) {
        #pragma unroll
        for (int u = 0; u < 4; u++) {
            const int blk = 4 * g + u;

            if (blk + 3 < NBLK) {
                const float* xb = xp + (size_t)(blk + 3) * TB * BN;
                #pragma unroll
                for (int t = 0; t < TB; t++)
                    buf[(u + 3) & 3][t] = xb[t * BN];
            }
            const float* xc = buf[u & 3];

            // ---- head: sg, maskf, ds from z (exact R5) ----
            float sg[TB];
            float maskf = 0.0f;
            #pragma unroll
            for (int t = 0; t < TB; t++) {
                sg[t] = (z[t] == 1.0f) ? 1.0f : 0.0f;
                if (sg[t] != 0.0f) maskf = 1.0f;
            }

            float a_at = 0.0f;
            #pragma unroll
            for (int t = 0; t < TB; t++)
                if (sg[t] != 0.0f) a_at += ppow[t + 1] * a;
            a_at += inv_p;

            int ds = 0;
            #pragma unroll
            for (int t = 0; t < TB; t++)
                if (z[t] > 1.0f) ds++;

            float pds = ppow[0];
            #pragma unroll
            for (int k = 1; k <= TB; k++)
                if (ds == k) pds = ppow[k];

            const float new_a = a_at * pds;
            a = (maskf != 0.0f) ? new_a : (ppow[TB] * a);

            // ---- refractory masking + carry-in (exact R5) ----
            const float v_init = vmem * (1.0f - maskf);
            float cur[TB];
            #pragma unroll
            for (int t = 0; t < TB; t++)
                cur[t] = (z[t] < maskf) ? 0.0f : xc[t];
            cur[0] = cur[0] + beta * v_init;

            // ---- causal decayed sums, S-MAJOR (bit-identical per-t order,
            //      8 independent FMA chains interleaved) ----
            float m[TB];
            #pragma unroll
            for (int t = 0; t < TB; t++) m[t] = 0.0f;
            #pragma unroll
            for (int s = 0; s < TB; s++) {
                #pragma unroll
                for (int t = s; t < TB; t++)
                    m[t] += bpow[t - s] * cur[s];   // ascending s per t (exact)
            }

            // ---- threshold (exact R5) ----
            float f[TB];
            #pragma unroll
            for (int t = 0; t < TB; t++) {
                const float vth = 1.0f + bb * (ppow[t + 1] * a);
                f[t] = ((m[t] - vth) > 0.0f) ? 1.0f : 0.0f;
            }
            const float mlast = m[TB - 1];

            // ---- z = double cumsum; emit spikes (exact R5) ----
            float* ob = op + (size_t)blk * TB * BN;
            float c = 0.0f, zr = 0.0f;
            #pragma unroll
            for (int t = 0; t < TB; t++) {
                c  += f[t];
                zr += c;
                z[t] = zr;
                ob[t * BN] = (zr == 1.0f) ? 1.0f : 0.0f;
            }

            vmem = mlast;
        }
    }
}

extern "C" void kernel_launch(void* const* d_in, const int* in_sizes, int n_in,
                              void* d_out, int out_size)
{
    const float* x        = (const float*)d_in[0];
    const float* beta_raw = (const float*)d_in[1];
    const float* p_raw    = (const float*)d_in[2];
    const float* b_raw    = (const float*)d_in[3];
    float* out = (float*)d_out;

    blocks_snn_kernel<<<BN / CTA, CTA>>>(x, beta_raw, p_raw, b_raw, out);
}